// round 2
// baseline (speedup 1.0000x reference)
#include <cuda_runtime.h>
#include <math_constants.h>

// Problem constants
#define BB 16
#define NN 1024
#define MM 8192
#define MSPLIT 8
#define MCHUNK (MM / MSPLIT)      // 1024 targets per block
#define NTILES 4                  // 1024 binder points / 256 threads
#define TPB 256
#define KSEL 204                  // int(0.2 * 1024)

// Scratch (no device allocation allowed) — fully overwritten every launch.
__device__ float g_min_d2[MSPLIT * BB * NN];       // [split][b][n]
__device__ float g_repel [MSPLIT * BB * NTILES];   // [split][b*4+tile]

__global__ void __launch_bounds__(TPB) pair_kernel(
    const float* __restrict__ binder,   // [16,1024,3]
    const float* __restrict__ target)   // [8192,3]
{
    __shared__ float4 s_tgt[MCHUNK];    // 16 KB
    __shared__ float  s_red[TPB];

    const int bx    = blockIdx.x;           // 0..63 : b*4 + ntile
    const int b     = bx >> 2;
    const int n     = ((bx & 3) << 8) + threadIdx.x;
    const int mbase = blockIdx.y * MCHUNK;

    // Cooperative target tile load (broadcast-read later, conflict-free).
    for (int j = threadIdx.x; j < MCHUNK; j += TPB) {
        const float* t = target + (size_t)(mbase + j) * 3;
        s_tgt[j] = make_float4(t[0], t[1], t[2], 0.f);
    }
    const float* p = binder + (size_t)(b * NN + n) * 3;
    const float px = p[0], py = p[1], pz = p[2];
    __syncthreads();

    // Two accumulator lanes to break FMNMX/FFMA dependency chains.
    float mind2a = CUDART_INF_F, mind2b = CUDART_INF_F;
    float repa = 0.f, repb = 0.f;

    #pragma unroll 4
    for (int j = 0; j < MCHUNK; j += 2) {
        float4 t0 = s_tgt[j];
        float4 t1 = s_tgt[j + 1];

        float dx0 = px - t0.x, dy0 = py - t0.y, dz0 = pz - t0.z;
        float dx1 = px - t1.x, dy1 = py - t1.y, dz1 = pz - t1.z;

        float d20 = fmaf(dx0, dx0, fmaf(dy0, dy0, dz0 * dz0));
        float d21 = fmaf(dx1, dx1, fmaf(dy1, dy1, dz1 * dz1));

        mind2a = fminf(mind2a, d20);
        mind2b = fminf(mind2b, d21);

        if (d20 < 9.f) {                 // rare (~0.25%)
            float c = 3.f - sqrtf(d20);
            repa = fmaf(c, c, repa);
        }
        if (d21 < 9.f) {
            float c = 3.f - sqrtf(d21);
            repb = fmaf(c, c, repb);
        }
    }

    g_min_d2[blockIdx.y * (BB * NN) + b * NN + n] = fminf(mind2a, mind2b);

    // Block-reduce repel partial.
    s_red[threadIdx.x] = repa + repb;
    __syncthreads();
    for (int s = TPB / 2; s > 0; s >>= 1) {
        if (threadIdx.x < s) s_red[threadIdx.x] += s_red[threadIdx.x + s];
        __syncthreads();
    }
    if (threadIdx.x == 0)
        g_repel[blockIdx.y * (BB * NTILES) + bx] = s_red[0];
}

__global__ void __launch_bounds__(512) finalize_kernel(float* __restrict__ out)
{
    __shared__ float s_d[NN];
    __shared__ float s_red[512];
    const int b   = blockIdx.x;
    const int tid = threadIdx.x;

    // Reduce the MSPLIT min-d2 partials, take sqrt once per point.
    for (int n = tid; n < NN; n += 512) {
        float m = CUDART_INF_F;
        #pragma unroll
        for (int s = 0; s < MSPLIT; ++s)
            m = fminf(m, g_min_d2[s * (BB * NN) + b * NN + n]);
        s_d[n] = sqrtf(fmaxf(m, 0.f));
    }
    __syncthreads();

    // In-smem bitonic sort (ascending), 1024 elems, 512 threads.
    for (int k = 2; k <= NN; k <<= 1) {
        for (int j = k >> 1; j > 0; j >>= 1) {
            for (int i = tid; i < NN; i += 512) {
                int ixj = i ^ j;
                if (ixj > i) {
                    bool up = ((i & k) == 0);
                    float a = s_d[i], c = s_d[ixj];
                    if ((a > c) == up) { s_d[i] = c; s_d[ixj] = a; }
                }
            }
            __syncthreads();
        }
    }

    // Mean of the KSEL smallest.
    float acc = 0.f;
    for (int i = tid; i < KSEL; i += 512) acc += s_d[i];
    s_red[tid] = acc;
    __syncthreads();
    for (int s = 256; s > 0; s >>= 1) {
        if (tid < s) s_red[tid] += s_red[tid + s];
        __syncthreads();
    }
    const float attract = s_red[0] / (float)KSEL;
    __syncthreads();   // protect s_red[0] before reuse

    // Sum 32 repel partials for this batch.
    float racc = 0.f;
    if (tid < MSPLIT * NTILES) {
        int sp = tid >> 2, t = tid & 3;
        racc = g_repel[sp * (BB * NTILES) + b * NTILES + t];
    }
    s_red[tid] = racc;
    __syncthreads();
    for (int s = 16; s > 0; s >>= 1) {
        if (tid < s) s_red[tid] += s_red[tid + s];
        __syncthreads();
    }

    if (tid == 0)
        out[b] = 10.0f * attract + 5.0f * s_red[0];
}

extern "C" void kernel_launch(void* const* d_in, const int* in_sizes, int n_in,
                              void* d_out, int out_size)
{
    const float* binder = (const float*)d_in[0];   // 16*1024*3
    const float* target = (const float*)d_in[1];   // 8192*3
    float* out = (float*)d_out;                    // 16

    dim3 grid(BB * NTILES, MSPLIT);                // 64 x 8 = 512 blocks
    pair_kernel<<<grid, TPB>>>(binder, target);
    finalize_kernel<<<BB, 512>>>(out);
}

// round 3
// speedup vs baseline: 1.1108x; 1.1108x over previous
#include <cuda_runtime.h>
#include <math_constants.h>

// Problem constants
#define BB 16
#define NN 1024
#define MM 8192
#define MSPLIT 16
#define MCHUNK (MM / MSPLIT)      // 512 targets per block
#define TPB 256
#define PPT 4                     // binder points per thread (256*4 = 1024 = NN)
#define KSEL 204                  // int(0.2 * 1024)

// Scratch (no device allocation allowed) — fully overwritten every launch.
__device__ float g_min_d2[MSPLIT * BB * NN];   // [split][b][n] : c + min_s (unclamped d2 partial-min)
__device__ float g_repel [MSPLIT * BB];        // [split][b]

__global__ void __launch_bounds__(TPB) pair_kernel(
    const float* __restrict__ binder,   // [16,1024,3]
    const float* __restrict__ target)   // [8192,3]
{
    __shared__ float4 s_tgt[MCHUNK];    // 8 KB : {-2x, -2y, -2z, |t|^2}
    __shared__ float  s_warp[TPB / 32];

    const int b     = blockIdx.x;       // batch
    const int split = blockIdx.y;       // M split
    const int tid   = threadIdx.x;
    const int mbase = split * MCHUNK;

    // Preprocess target tile: t' = (-2t, |t|^2) so d2 = |p|^2 + s,
    // s = t'w + p.t'  (pure FFMA chain, 3 ops per pair).
    for (int j = tid; j < MCHUNK; j += TPB) {
        const float* t = target + (size_t)(mbase + j) * 3;
        float x = t[0], y = t[1], z = t[2];
        s_tgt[j] = make_float4(-2.f * x, -2.f * y, -2.f * z,
                               fmaf(x, x, fmaf(y, y, z * z)));
    }

    // Per-thread register block of PPT binder points.
    float px[PPT], py[PPT], pz[PPT], cc[PPT], th[PPT];
    #pragma unroll
    for (int k = 0; k < PPT; ++k) {
        int n = tid + TPB * k;
        const float* p = binder + (size_t)(b * NN + n) * 3;
        px[k] = p[0]; py[k] = p[1]; pz[k] = p[2];
        cc[k] = fmaf(px[k], px[k], fmaf(py[k], py[k], pz[k] * pz[k]));
        th[k] = 9.f - cc[k];            // s < th  <=>  d2 < 9  <=>  dist < 3
    }
    __syncthreads();

    // Dual min accumulators per point (break FMNMX chains); shared repel acc.
    float m0[PPT], m1[PPT];
    #pragma unroll
    for (int k = 0; k < PPT; ++k) { m0[k] = CUDART_INF_F; m1[k] = CUDART_INF_F; }
    float rep = 0.f;

    #pragma unroll 4
    for (int j = 0; j < MCHUNK; j += 2) {
        float4 t0 = s_tgt[j];
        float4 t1 = s_tgt[j + 1];
        #pragma unroll
        for (int k = 0; k < PPT; ++k) {
            float s0 = fmaf(pz[k], t0.z, fmaf(py[k], t0.y, fmaf(px[k], t0.x, t0.w)));
            float s1 = fmaf(pz[k], t1.z, fmaf(py[k], t1.y, fmaf(px[k], t1.x, t1.w)));
            m0[k] = fminf(m0[k], s0);
            m1[k] = fminf(m1[k], s1);
            // Rare clash path (~0.25% of pairs): one test per 2 targets.
            if (__builtin_expect(fminf(s0, s1) < th[k], 0)) {
                if (s0 < th[k]) {
                    float d2 = fmaxf(cc[k] + s0, 0.f);
                    float cl = 3.f - sqrtf(d2);
                    rep = fmaf(cl, cl, rep);
                }
                if (s1 < th[k]) {
                    float d2 = fmaxf(cc[k] + s1, 0.f);
                    float cl = 3.f - sqrtf(d2);
                    rep = fmaf(cl, cl, rep);
                }
            }
        }
    }

    // Per-point partial min-d2 (unclamped; clamp is monotone, done in finalize).
    #pragma unroll
    for (int k = 0; k < PPT; ++k) {
        int n = tid + TPB * k;
        g_min_d2[split * (BB * NN) + b * NN + n] = cc[k] + fminf(m0[k], m1[k]);
    }

    // Block-reduce repel partial (shfl + one smem hop).
    #pragma unroll
    for (int off = 16; off; off >>= 1)
        rep += __shfl_xor_sync(0xffffffffu, rep, off);
    const int lane = tid & 31, wid = tid >> 5;
    if (lane == 0) s_warp[wid] = rep;
    __syncthreads();
    if (tid == 0) {
        float r = 0.f;
        #pragma unroll
        for (int w = 0; w < TPB / 32; ++w) r += s_warp[w];
        g_repel[split * BB + b] = r;
    }
}

// One block per batch: min over splits, radix-select K smallest d2,
// mean of their sqrt, combine with repel.
__global__ void __launch_bounds__(256) finalize_kernel(float* __restrict__ out)
{
    __shared__ unsigned hist[256];
    __shared__ unsigned sh_sel, sh_rank;
    __shared__ float    s_fred[8];
    __shared__ unsigned s_ured[8];

    const int b    = blockIdx.x;
    const int tid  = threadIdx.x;
    const int lane = tid & 31, wid = tid >> 5;

    // 1. Reduce split partial mins; keep values + order-preserving uint keys
    //    in registers (non-negative floats: IEEE bits order == value order).
    float vals[4]; unsigned keys[4];
    #pragma unroll
    for (int i = 0; i < 4; ++i) {
        int n = tid + 256 * i;
        float m = CUDART_INF_F;
        #pragma unroll
        for (int s = 0; s < MSPLIT; ++s)
            m = fminf(m, g_min_d2[s * (BB * NN) + b * NN + n]);
        float d2 = fmaxf(m, 0.f);
        vals[i] = d2;
        keys[i] = __float_as_uint(d2);
    }

    if (tid == 0) sh_rank = KSEL;       // 1-based rank of the K-th smallest
    __syncthreads();

    // 2. 4-pass MSB radix select (8 bits/pass) for the KSEL-th smallest key.
    unsigned prefix = 0, prefmask = 0;
    #pragma unroll
    for (int pass = 0; pass < 4; ++pass) {
        const int shift = 24 - 8 * pass;
        hist[tid] = 0;
        __syncthreads();
        #pragma unroll
        for (int i = 0; i < 4; ++i)
            if ((keys[i] & prefmask) == prefix)
                atomicAdd(&hist[(keys[i] >> shift) & 255u], 1u);
        __syncthreads();
        if (tid < 32) {                 // warp 0: scan 256 bins, pick bucket
            unsigned c8[8], tot = 0;
            #pragma unroll
            for (int i = 0; i < 8; ++i) { c8[i] = hist[tid * 8 + i]; tot += c8[i]; }
            unsigned incl = tot;
            #pragma unroll
            for (int off = 1; off < 32; off <<= 1) {
                unsigned v = __shfl_up_sync(0xffffffffu, incl, off);
                if (tid >= off) incl += v;
            }
            unsigned excl = incl - tot;
            unsigned r = sh_rank;
            __syncwarp();
            if (r > excl && r <= incl) {          // exactly one lane
                unsigned run = excl, sel = 0, nr = 0;
                #pragma unroll
                for (int i = 0; i < 8; ++i) {
                    if (run < r && r <= run + c8[i]) { sel = tid * 8 + i; nr = r - run; }
                    run += c8[i];
                }
                sh_sel  = sel;
                sh_rank = nr;
            }
        }
        __syncthreads();
        prefix   |= sh_sel << shift;
        prefmask |= 0xFFu   << shift;
    }
    const unsigned T = prefix;          // exact key of the KSEL-th smallest

    // 3. Sum sqrt(d2) for keys strictly below T; tie-correct with T itself.
    float ssum = 0.f; unsigned scnt = 0;
    #pragma unroll
    for (int i = 0; i < 4; ++i)
        if (keys[i] < T) { ssum += sqrtf(vals[i]); scnt++; }
    #pragma unroll
    for (int off = 16; off; off >>= 1) {
        ssum += __shfl_xor_sync(0xffffffffu, ssum, off);
        scnt += __shfl_xor_sync(0xffffffffu, scnt, off);
    }
    if (lane == 0) { s_fred[wid] = ssum; s_ured[wid] = scnt; }
    __syncthreads();

    if (tid == 0) {
        float st = 0.f; unsigned ct = 0;
        #pragma unroll
        for (int w = 0; w < 8; ++w) { st += s_fred[w]; ct += s_ured[w]; }
        float rep = 0.f;
        #pragma unroll
        for (int s = 0; s < MSPLIT; ++s) rep += g_repel[s * BB + b];
        float attract = (st + (float)(KSEL - ct) * sqrtf(__uint_as_float(T)))
                        * (1.f / (float)KSEL);
        out[b] = 10.f * attract + 5.f * rep;
    }
}

extern "C" void kernel_launch(void* const* d_in, const int* in_sizes, int n_in,
                              void* d_out, int out_size)
{
    const float* binder = (const float*)d_in[0];   // 16*1024*3
    const float* target = (const float*)d_in[1];   // 8192*3
    float* out = (float*)d_out;                    // 16

    dim3 grid(BB, MSPLIT);                         // 16 x 16 = 256 blocks
    pair_kernel<<<grid, TPB>>>(binder, target);
    finalize_kernel<<<BB, 256>>>(out);
}

// round 4
// speedup vs baseline: 1.5333x; 1.3804x over previous
#include <cuda_runtime.h>
#include <math_constants.h>

// Problem constants
#define BB 16
#define NN 1024
#define MM 8192
#define MSPLIT 32
#define MCHUNK (MM / MSPLIT)      // 256 targets per block
#define TPB 256
#define PPT 4                     // binder points per thread
#define KSEL 204                  // int(0.2 * 1024)

// Scratch (no device allocation allowed) — re-initialized by init_kernel each launch.
__device__ unsigned g_min_d2u[BB * NN];   // order-preserving bits of clamped min d2
__device__ float    g_repel  [BB];

__global__ void __launch_bounds__(256) init_kernel()
{
    int i = blockIdx.x * 256 + threadIdx.x;
    if (i < BB * NN) g_min_d2u[i] = 0x7F800000u;   // +inf
    if (i < BB)      g_repel[i]   = 0.f;
}

__global__ void __launch_bounds__(TPB) pair_kernel(
    const float* __restrict__ binder,   // [16,1024,3]
    const float* __restrict__ target)   // [8192,3]
{
    __shared__ float4 s_tgt[MCHUNK];    // 4 KB : {-2x, -2y, -2z, |t|^2}
    __shared__ float  s_warp[TPB / 32];

    const int b     = blockIdx.x;       // batch
    const int split = blockIdx.y;       // M split
    const int tid   = threadIdx.x;
    const int mbase = split * MCHUNK;

    // t' = (-2t, |t|^2) so that s = t'.w + p.t'xyz and d2 = |p|^2 + s.
    for (int j = tid; j < MCHUNK; j += TPB) {
        const float* t = target + (size_t)(mbase + j) * 3;
        float x = t[0], y = t[1], z = t[2];
        s_tgt[j] = make_float4(-2.f * x, -2.f * y, -2.f * z,
                               fmaf(x, x, fmaf(y, y, z * z)));
    }

    float px[PPT], py[PPT], pz[PPT], cc[PPT], th[PPT];
    #pragma unroll
    for (int k = 0; k < PPT; ++k) {
        int n = tid + TPB * k;
        const float* p = binder + (size_t)(b * NN + n) * 3;
        px[k] = p[0]; py[k] = p[1]; pz[k] = p[2];
        cc[k] = fmaf(px[k], px[k], fmaf(py[k], py[k], pz[k] * pz[k]));
        th[k] = 9.f - cc[k];            // s < th  <=>  d2 < 9  <=>  dist < 3
    }
    __syncthreads();

    float m[PPT];
    #pragma unroll
    for (int k = 0; k < PPT; ++k) m[k] = CUDART_INF_F;
    float rep = 0.f;

    #pragma unroll 2
    for (int j = 0; j < MCHUNK; j += 2) {
        float4 t0 = s_tgt[j];
        float4 t1 = s_tgt[j + 1];

        float s0[PPT], s1[PPT], sm[PPT];
        float v = CUDART_INF_F;         // min_k (sm[k] - th[k]); <0 => some clash
        #pragma unroll
        for (int k = 0; k < PPT; ++k) {
            s0[k] = fmaf(pz[k], t0.z, fmaf(py[k], t0.y, fmaf(px[k], t0.x, t0.w)));
            s1[k] = fmaf(pz[k], t1.z, fmaf(py[k], t1.y, fmaf(px[k], t1.x, t1.w)));
            sm[k] = fminf(s0[k], s1[k]);
            m[k]  = fminf(m[k], sm[k]);
            v     = fminf(v, sm[k] - th[k]);
        }

        // ONE rare divergence point per iteration (p_taken ~ 15% per warp).
        if (__builtin_expect(v < 0.f, 0)) {
            #pragma unroll
            for (int k = 0; k < PPT; ++k) {
                if (sm[k] < th[k]) {
                    if (s0[k] < th[k]) {
                        float cl = 3.f - sqrtf(fmaxf(cc[k] + s0[k], 0.f));
                        rep = fmaf(cl, cl, rep);
                    }
                    if (s1[k] < th[k]) {
                        float cl = 3.f - sqrtf(fmaxf(cc[k] + s1[k], 0.f));
                        rep = fmaf(cl, cl, rep);
                    }
                }
            }
        }
    }

    // Global min-reduce across splits via uint atomicMin (non-negative floats:
    // IEEE bit pattern order == value order; clamp first).
    #pragma unroll
    for (int k = 0; k < PPT; ++k) {
        int n = tid + TPB * k;
        float d2 = fmaxf(cc[k] + m[k], 0.f);
        atomicMin(&g_min_d2u[b * NN + n], __float_as_uint(d2));
    }

    // Block-reduce repel, one atomicAdd per block.
    #pragma unroll
    for (int off = 16; off; off >>= 1)
        rep += __shfl_xor_sync(0xffffffffu, rep, off);
    const int lane = tid & 31, wid = tid >> 5;
    if (lane == 0) s_warp[wid] = rep;
    __syncthreads();
    if (tid == 0) {
        float r = 0.f;
        #pragma unroll
        for (int w = 0; w < TPB / 32; ++w) r += s_warp[w];
        atomicAdd(&g_repel[b], r);
    }
}

// One block per batch: radix-select the KSEL-th smallest d2, mean of sqrt of
// the KSEL smallest (tie-corrected), combine with repel.
__global__ void __launch_bounds__(256) finalize_kernel(float* __restrict__ out)
{
    __shared__ unsigned hist[256];
    __shared__ unsigned sh_sel, sh_rank;
    __shared__ float    s_fred[8];
    __shared__ unsigned s_ured[8];

    const int b    = blockIdx.x;
    const int tid  = threadIdx.x;
    const int lane = tid & 31, wid = tid >> 5;

    unsigned keys[4];
    #pragma unroll
    for (int i = 0; i < 4; ++i)
        keys[i] = g_min_d2u[b * NN + tid + 256 * i];

    if (tid == 0) sh_rank = KSEL;
    __syncthreads();

    unsigned prefix = 0, prefmask = 0;
    #pragma unroll
    for (int pass = 0; pass < 4; ++pass) {
        const int shift = 24 - 8 * pass;
        hist[tid] = 0;
        __syncthreads();
        #pragma unroll
        for (int i = 0; i < 4; ++i)
            if ((keys[i] & prefmask) == prefix)
                atomicAdd(&hist[(keys[i] >> shift) & 255u], 1u);
        __syncthreads();
        if (tid < 32) {
            unsigned c8[8], tot = 0;
            #pragma unroll
            for (int i = 0; i < 8; ++i) { c8[i] = hist[tid * 8 + i]; tot += c8[i]; }
            unsigned incl = tot;
            #pragma unroll
            for (int off = 1; off < 32; off <<= 1) {
                unsigned x = __shfl_up_sync(0xffffffffu, incl, off);
                if (tid >= off) incl += x;
            }
            unsigned excl = incl - tot;
            unsigned r = sh_rank;
            __syncwarp();
            if (r > excl && r <= incl) {
                unsigned run = excl, sel = 0, nr = 0;
                #pragma unroll
                for (int i = 0; i < 8; ++i) {
                    if (run < r && r <= run + c8[i]) { sel = tid * 8 + i; nr = r - run; }
                    run += c8[i];
                }
                sh_sel  = sel;
                sh_rank = nr;
            }
        }
        __syncthreads();
        prefix   |= sh_sel << shift;
        prefmask |= 0xFFu   << shift;
    }
    const unsigned T = prefix;          // key of the KSEL-th smallest

    float ssum = 0.f; unsigned scnt = 0;
    #pragma unroll
    for (int i = 0; i < 4; ++i)
        if (keys[i] < T) { ssum += sqrtf(__uint_as_float(keys[i])); scnt++; }
    #pragma unroll
    for (int off = 16; off; off >>= 1) {
        ssum += __shfl_xor_sync(0xffffffffu, ssum, off);
        scnt += __shfl_xor_sync(0xffffffffu, scnt, off);
    }
    if (lane == 0) { s_fred[wid] = ssum; s_ured[wid] = scnt; }
    __syncthreads();

    if (tid == 0) {
        float st = 0.f; unsigned ct = 0;
        #pragma unroll
        for (int w = 0; w < 8; ++w) { st += s_fred[w]; ct += s_ured[w]; }
        float attract = (st + (float)(KSEL - ct) * sqrtf(__uint_as_float(T)))
                        * (1.f / (float)KSEL);
        out[b] = 10.f * attract + 5.f * g_repel[b];
    }
}

extern "C" void kernel_launch(void* const* d_in, const int* in_sizes, int n_in,
                              void* d_out, int out_size)
{
    const float* binder = (const float*)d_in[0];   // 16*1024*3
    const float* target = (const float*)d_in[1];   // 8192*3
    float* out = (float*)d_out;                    // 16

    init_kernel<<<(BB * NN + 255) / 256, 256>>>();
    dim3 grid(BB, MSPLIT);                         // 16 x 32 = 512 blocks
    pair_kernel<<<grid, TPB>>>(binder, target);
    finalize_kernel<<<BB, 256>>>(out);
}